// round 17
// baseline (speedup 1.0000x reference)
#include <cuda_runtime.h>
#include <cstdint>

// Problem constants
#define BB 1024
#define TT 4096
#define LL 30
#define HH 32
#define PP 2

// ---------------------------------------------------------------------------
// Accurate tanh (encoder only; abs err ~1e-7):
// tanh(x) = 1 - 2/(exp2(2*log2e*x)+1)
// ---------------------------------------------------------------------------
__device__ __forceinline__ float ex2f(float x) {
    float r; asm("ex2.approx.ftz.f32 %0, %1;" : "=f"(r) : "f"(x)); return r;
}
__device__ __forceinline__ float rcpf(float x) {
    float r; asm("rcp.approx.ftz.f32 %0, %1;" : "=f"(r) : "f"(x)); return r;
}
__device__ __forceinline__ float tanh_acc(float x) {
    const float C = 2.885390081777927f;  // 2*log2(e)
    float e = ex2f(fminf(x * C, 30.0f));
    return 1.0f - 2.0f * rcpf(e + 1.0f);
}
// Fast tanh: single MUFU.TANH (measured effective error ~1e-6 on this data).
__device__ __forceinline__ float tanh_fast(float x) {
    float r; asm("tanh.approx.f32 %0, %1;" : "=f"(r) : "f"(x)); return r;
}

// ---------------------------------------------------------------------------
// Fully fused kernel: encoder + sequential Euler scan + epilogue.
// R10-proven scan shape: 8 lanes per batch element, 4 hidden units each,
// flat-7 scalar butterfly, 128 blocks x 64 threads (256 warps, 1/SMSP).
// NEW (R17): the kappa/a/xhat epilogue is computed inline at each z-store
// point (all-lane unpredicated math, lane-predicated stores, phi prefetched
// 2 iterations deep) — post_kernel is gone.
// ---------------------------------------------------------------------------
__global__ void __launch_bounds__(64, 1)
scan_kernel(const float* __restrict__ x,
            const float* __restrict__ phi,
            const float* __restrict__ ew1, const float* __restrict__ eb1,
            const float* __restrict__ ew2, const float* __restrict__ eb2,
            const float* __restrict__ fw1, const float* __restrict__ fb1,
            const float* __restrict__ fw2, const float* __restrict__ fb2,
            float* __restrict__ out)
{
    const int g = blockIdx.x * 64 + threadIdx.x;   // 0..8191
    const int b = g >> 3;                          // batch element
    const int q = g & 7;                           // lane within chain group
    const int j0 = q * 4;                          // first hidden unit

    // --- Register-resident ODE weights for this thread's 4 hidden units ---
    float w1a[4], w1b[4], b1s[4], w2a[4], w2b[4];
#pragma unroll
    for (int i = 0; i < 4; i++) {
        int j = j0 + i;
        w1a[i] = fw1[j];
        w1b[i] = fw1[HH + j];
        b1s[i] = fb1[j];
        w2a[i] = fw2[j * PP + 0];
        w2b[i] = fw2[j * PP + 1];
    }
    // b2 folded into lane 0's accumulation seed
    const float S0 = (q == 0) ? fb2[0] : 0.0f;
    const float S1 = (q == 0) ? fb2[1] : 0.0f;

    // --- Encoder: z0 = tanh(x[b,:30] @ ew1 + eb1) @ ew2 + eb2 (accurate) ---
    float z1, z2;
    {
        float acc0 = 0.f, acc1 = 0.f;
        const float* xb = x + (size_t)b * TT;
#pragma unroll
        for (int i = 0; i < 4; i++) {
            int j = j0 + i;
            float u = eb1[j];
#pragma unroll
            for (int l = 0; l < LL; l++)
                u = fmaf(xb[l], ew1[l * HH + j], u);
            float th = tanh_acc(u);
            acc0 = fmaf(th, ew2[j * PP + 0], acc0);
            acc1 = fmaf(th, ew2[j * PP + 1], acc1);
        }
        acc0 += __shfl_xor_sync(0xffffffffu, acc0, 1);
        acc1 += __shfl_xor_sync(0xffffffffu, acc1, 1);
        acc0 += __shfl_xor_sync(0xffffffffu, acc0, 2);
        acc1 += __shfl_xor_sync(0xffffffffu, acc1, 2);
        acc0 += __shfl_xor_sync(0xffffffffu, acc0, 4);
        acc1 += __shfl_xor_sync(0xffffffffu, acc1, 4);
        z1 = acc0 + eb2[0];
        z2 = acc1 + eb2[1];
    }

    // Output regions: [xhat (B*T) | a (B*T*P) | z (B*T*P)], per-b vector views
    float4* zo4 = reinterpret_cast<float4*>(out + 3ull * BB * TT) + (size_t)b * (TT / 2);
    float4* ao4 = reinterpret_cast<float4*>(out + 1ull * BB * TT) + (size_t)b * (TT / 2);
    float2* xo2 = reinterpret_cast<float2*>(out)                  + (size_t)b * (TT / 2);
    const float4* phv = reinterpret_cast<const float4*>(phi)      + (size_t)b * (TT / 2);

    // phi prefetch ring, depth 2 (2 iterations = ~620 cyc >= DRAM 577).
    // All 8 lanes of a group load the same address (L1 broadcast) — no branch.
    float4 ph0 = phv[0];
    float4 ph1 = phv[1];

    // --- One Euler step (R10-proven) ---
    auto STEP = [&]() {
        float u0 = fmaf(z1, w1a[0], fmaf(z2, w1b[0], b1s[0]));
        float u1 = fmaf(z1, w1a[1], fmaf(z2, w1b[1], b1s[1]));
        float u2 = fmaf(z1, w1a[2], fmaf(z2, w1b[2], b1s[2]));
        float u3 = fmaf(z1, w1a[3], fmaf(z2, w1b[3], b1s[3]));
        float t0 = tanh_fast(u0);
        float t1 = tanh_fast(u1);
        float t2 = tanh_fast(u2);
        float t3 = tanh_fast(u3);
        float p0 = fmaf(t1, w2a[1], fmaf(t0, w2a[0], S0))
                 + fmaf(t3, w2a[3], t2 * w2a[2]);
        float p1 = fmaf(t1, w2b[1], fmaf(t0, w2b[0], S1))
                 + fmaf(t3, w2b[3], t2 * w2b[2]);
        float s01 = __shfl_xor_sync(0xffffffffu, p0, 1);
        float s02 = __shfl_xor_sync(0xffffffffu, p0, 2);
        float s03 = __shfl_xor_sync(0xffffffffu, p0, 3);
        float s04 = __shfl_xor_sync(0xffffffffu, p0, 4);
        float s05 = __shfl_xor_sync(0xffffffffu, p0, 5);
        float s06 = __shfl_xor_sync(0xffffffffu, p0, 6);
        float s07 = __shfl_xor_sync(0xffffffffu, p0, 7);
        float s11 = __shfl_xor_sync(0xffffffffu, p1, 1);
        float s12 = __shfl_xor_sync(0xffffffffu, p1, 2);
        float s13 = __shfl_xor_sync(0xffffffffu, p1, 3);
        float s14 = __shfl_xor_sync(0xffffffffu, p1, 4);
        float s15 = __shfl_xor_sync(0xffffffffu, p1, 5);
        float s16 = __shfl_xor_sync(0xffffffffu, p1, 6);
        float s17 = __shfl_xor_sync(0xffffffffu, p1, 7);
        p0 = ((p0 + s01) + (s02 + s03)) + ((s04 + s05) + (s06 + s07));
        p1 = ((p1 + s11) + (s12 + s13)) + ((s14 + s15) + (s16 + s17));
        z1 += p0;
        z2 += p1;
    };

    // --- 4095 steps, unrolled by 2; fused epilogue per 2 time entries ---
#pragma unroll 1
    for (int k = 0; k < 2047; ++k) {
        float az1 = z1, az2 = z2;          // entry 2k
        STEP();                            // entry 2k+1
        // ---- fused epilogue for entries 2k (az) and 2k+1 (z) ----
        float4 ph = ph0;                   // phi for entries 2k, 2k+1
        ph0 = ph1;
        int nidx = (k + 2 <= 2047) ? (k + 2) : 2047;
        ph1 = phv[nidx];                   // consumed 2 iterations from now
        float k1a = tanh_fast(az1), k2a = tanh_fast(az2);
        float k1b = tanh_fast(z1),  k2b = tanh_fast(z2);
        float a0a = k1a * (1.0f - k2a);
        float a0b = k1b * (1.0f - k2b);
        float x0 = fmaf(a0a, ph.x, k2a * ph.y);
        float x1 = fmaf(a0b, ph.z, k2b * ph.w);
        if (k == 0) { x0 = 0.0f; x1 = 0.0f; }   // xhat[:, :P] = 0
        if (q == 0) {
            zo4[k] = make_float4(az1, az2, z1, z2);
            ao4[k] = make_float4(a0a, k2a, a0b, k2b);
            xo2[k] = make_float2(x0, x1);
        }
        STEP();                            // entry 2k+2
    }
    {
        float az1 = z1, az2 = z2;          // entry 4094
        STEP();                            // entry 4095
        float4 ph = ph0;
        float k1a = tanh_fast(az1), k2a = tanh_fast(az2);
        float k1b = tanh_fast(z1),  k2b = tanh_fast(z2);
        float a0a = k1a * (1.0f - k2a);
        float a0b = k1b * (1.0f - k2b);
        float x0 = fmaf(a0a, ph.x, k2a * ph.y);
        float x1 = fmaf(a0b, ph.z, k2b * ph.w);
        if (q == 0) {
            zo4[2047] = make_float4(az1, az2, z1, z2);
            ao4[2047] = make_float4(a0a, k2a, a0b, k2b);
            xo2[2047] = make_float2(x0, x1);
        }
    }
}

// ---------------------------------------------------------------------------
extern "C" void kernel_launch(void* const* d_in, const int* in_sizes, int n_in,
                              void* d_out, int out_size)
{
    const float* x   = (const float*)d_in[0];
    const float* phi = (const float*)d_in[1];
    const float* ew1 = (const float*)d_in[2];
    const float* eb1 = (const float*)d_in[3];
    const float* ew2 = (const float*)d_in[4];
    const float* eb2 = (const float*)d_in[5];
    const float* fw1 = (const float*)d_in[6];
    const float* fb1 = (const float*)d_in[7];
    const float* fw2 = (const float*)d_in[8];
    const float* fb2 = (const float*)d_in[9];
    float* out = (float*)d_out;

    // Single fused kernel: 8192 threads = 8 lanes per chain;
    // 128 blocks x 64 threads -> 256 warps, one per SMSP across 128 SMs.
    scan_kernel<<<128, 64>>>(x, phi, ew1, eb1, ew2, eb2,
                             fw1, fb1, fw2, fb2, out);
}